// round 13
// baseline (speedup 1.0000x reference)
#include <cuda_runtime.h>
#include <cstdint>

#define NC         100000
#define FEAT       256
#define BATCH      16384
#define F4         64                          // FEAT / 4
#define THREADS    256
#define WPB        8
#define BL_THREADS 128
#define BL_BLOCKS  (BATCH / BL_THREADS)        // 128
#define CPB        128                         // classes scanned per block
#define CLS_BLOCKS ((NC + CPB - 1) / CPB)      // 782

// contrib_c = Q - 1.9602 (c.s) + 0.9801 n||c||^2 - (0.0199/n) ||s||^2
// (expansion of sum_i ||x_i - t||^2 with t = 0.99 c + 0.01 s / n)
#define A_D 1.9602f
#define A_E 0.9801f
#define A_S 0.0199f

// Scratch — zero at module load; classpass restores the zero invariant on
// g_head. g_next needs no invariant (every slot overwritten each replay).
__device__ int      g_head[NC];      // linked-list head, idx+1 (0 = empty)
__device__ int      g_next[BATCH];
__device__ float    g_loss;
__device__ unsigned g_done;

__device__ __forceinline__ float dot4(float4 a, float4 b) {
    return a.x*b.x + a.y*b.y + a.z*b.z + a.w*b.w;
}
__device__ __forceinline__ void add4(float4& a, float4 b) {
    a.x += b.x; a.y += b.y; a.z += b.z; a.w += b.w;
}

// ---------------------------------------------------------------------------
// Launch 1: build per-class linked lists. One atomicExch per sample, spread
// over ~15.5K distinct addresses. No feature data touched.
// ---------------------------------------------------------------------------
__global__ __launch_bounds__(BL_THREADS) void buildlist(const int* __restrict__ label) {
    int s = blockIdx.x * BL_THREADS + threadIdx.x;
    g_next[s] = atomicExch(&g_head[label[s]], s + 1);
}

// ---------------------------------------------------------------------------
// Launch 2: everything else. Scan g_head (coalesced 400 KB), compact touched
// classes, then one warp per class: walk the chain accumulating s and Q in
// registers (center row load issued first to overlap the serial next-hops),
// then close the class with pure register math + one warp reduce.
// ---------------------------------------------------------------------------
__global__ __launch_bounds__(THREADS) void classpass(const float* __restrict__ x,
                                                     const float* __restrict__ center,
                                                     float* __restrict__ out) {
    __shared__ int   s_m;
    __shared__ int   s_cls[CPB];
    __shared__ int   s_head[CPB];
    __shared__ float s_wsum[WPB];

    int tid  = threadIdx.x;
    int lane = tid & 31;
    int wid  = tid >> 5;

    if (tid == 0) s_m = 0;
    __syncthreads();

    if (tid < CPB) {
        int c = blockIdx.x * CPB + tid;
        if (c < NC) {
            int h = g_head[c];                 // coalesced 4B scan
            if (h != 0) {
                int p = atomicAdd(&s_m, 1);    // smem atomic
                s_cls[p]  = c;
                s_head[p] = h;
                g_head[c] = 0;                 // restore invariant
            }
        }
    }
    __syncthreads();

    int m = s_m;                               // ~20 touched classes per block
    float acc = 0.f;

    for (int i = wid; i < m; i += WPB) {
        int c = s_cls[i];
        int a = s_head[i] - 1;

        // Center row: issue first so it overlaps the chain walk.
        const float4* cr = reinterpret_cast<const float4*>(center) + (size_t)c * F4;
        float4 c0 = cr[lane], c1 = cr[lane + 32];

        float4 s0 = make_float4(0.f, 0.f, 0.f, 0.f);
        float4 s1 = make_float4(0.f, 0.f, 0.f, 0.f);
        float  q  = 0.f;
        float  n  = 0.f;
        while (a >= 0) {                       // avg ~1.06 hops per class
            int nx = g_next[a];                // serial dependence (next hop)
            const float4* xr = reinterpret_cast<const float4*>(x) + (size_t)a * F4;
            float4 v0 = xr[lane], v1 = xr[lane + 32];
            add4(s0, v0);
            add4(s1, v1);
            q += dot4(v0, v0) + dot4(v1, v1);
            n += 1.f;
            a  = nx - 1;
        }

        float dterm = dot4(c0, s0) + dot4(c1, s1);   // lane partial of c.s
        float eterm = dot4(c0, c0) + dot4(c1, c1);   // lane partial of ||c||^2
        float sterm = dot4(s0, s0) + dot4(s1, s1);   // lane partial of ||s||^2
        // q, dterm, eterm, sterm are lane partials; n is warp-uniform.
        acc += q - A_D * dterm + A_E * n * eterm - A_S * sterm / n;
    }

    #pragma unroll
    for (int o = 16; o > 0; o >>= 1)
        acc += __shfl_down_sync(0xFFFFFFFFu, acc, o);
    if (lane == 0) s_wsum[wid] = acc;
    __syncthreads();

    if (tid == 0) {
        float b = 0.f;
        #pragma unroll
        for (int i = 0; i < WPB; i++) b += s_wsum[i];
        atomicAdd(&g_loss, b);                 // 782 ops, one addr: ~1 cyc each
        __threadfence();
        if (atomicAdd(&g_done, 1u) == (unsigned)(gridDim.x - 1)) {
            out[0] = __ldcg(&g_loss) * (1.f / ((float)BATCH * (float)FEAT));
            g_loss = 0.f;                      // restore invariants
            g_done = 0u;
        }
    }
}

extern "C" void kernel_launch(void* const* d_in, const int* in_sizes, int n_in,
                              void* d_out, int out_size) {
    const float* x      = (const float*)d_in[0];   // batch_feature [16384, 256] f32
    const int*   label  = (const int*)d_in[1];     // batch_label   [16384] int32
    const float* center = (const float*)d_in[2];   // center_feature[100000, 256] f32
    float* out = (float*)d_out;

    buildlist<<<BL_BLOCKS, BL_THREADS>>>(label);
    classpass<<<CLS_BLOCKS, THREADS>>>(x, center, out);
}